// round 2
// baseline (speedup 1.0000x reference)
#include <cuda_runtime.h>
#include <cuda_bf16.h>

#define B_ 4
#define T_ 12
#define N_ 2000
#define K_ 10
#define F_ 64
#define H_ 8

// Scratch for y = x @ W^T  (B*T*N*F floats = 24.6 MB). Static __device__ array
// (allocation guards forbid cudaMalloc).
__device__ float g_y[B_ * T_ * N_ * F_];

// ---------------------------------------------------------------------------
// Kernel 1: y[row, f] = sum_fp x[row, fp] * W[f, fp]   (row = b*T*N + t*N + n)
// 1500 blocks x 256 threads; 64 rows per block; W transposed in smem (padded).
// ---------------------------------------------------------------------------
__global__ __launch_bounds__(256) void k_xw(const float* __restrict__ x,
                                            const float* __restrict__ W) {
    __shared__ float Wt[64][65];   // Wt[fp][f] = W[f][fp], pad avoids bank conflicts
    __shared__ float xs[16][64];

    const int tid = threadIdx.x;
    #pragma unroll 4
    for (int j = tid; j < 64 * 64; j += 256) {
        Wt[j & 63][j >> 6] = W[j];
    }
    const int f  = tid & 63;
    const int rg = tid >> 6;          // 0..3, each handles 4 rows per tile
    const long base = (long)blockIdx.x * 64;
    __syncthreads();

    for (int it = 0; it < 4; ++it) {
        const long rbase = base + it * 16;
        const float* xp = x + rbase * F_;
        #pragma unroll 4
        for (int j = tid; j < 16 * 64; j += 256) {
            ((float*)xs)[j] = xp[j];          // contiguous, fully coalesced
        }
        __syncthreads();

        float a0 = 0.f, a1 = 0.f, a2 = 0.f, a3 = 0.f;
        #pragma unroll
        for (int fp = 0; fp < 64; ++fp) {
            const float wv = Wt[fp][f];       // conflict-free, reused 4x
            a0 = fmaf(xs[rg * 4 + 0][fp], wv, a0);   // xs reads are broadcasts
            a1 = fmaf(xs[rg * 4 + 1][fp], wv, a1);
            a2 = fmaf(xs[rg * 4 + 2][fp], wv, a2);
            a3 = fmaf(xs[rg * 4 + 3][fp], wv, a3);
        }
        float* yp = g_y + rbase * F_;
        yp[(rg * 4 + 0) * F_ + f] = a0;
        yp[(rg * 4 + 1) * F_ + f] = a1;
        yp[(rg * 4 + 2) * F_ + f] = a2;
        yp[(rg * 4 + 3) * F_ + f] = a3;
        __syncthreads();
    }
}

// ---------------------------------------------------------------------------
// Kernel 2: per block = (node n, batch b). Loops t=0..11 sequentially so the
// temporal blend (0.8*agg[t] + 0.2*agg[t-1], with agg[t-1] UNBLENDED) is a
// register carry. 512 threads = (h = tid>>6, f = tid&63).
//   acc[h,f]   = sum_k exp(-d[n,k]^2*(h+1)/(8*36)) * y[b,t,idx[n,k],f]
//   out[...]   = relu(blend + bias[f])
// ---------------------------------------------------------------------------
__global__ __launch_bounds__(512) void k_gather(
    const float* __restrict__ dist,
    const float* __restrict__ bias,
    const int* __restrict__ nidx,      // int32! (JAX x64 disabled: randint -> i32)
    float* __restrict__ out) {

    __shared__ float sy[K_ * F_];    // 10 gathered y-rows
    __shared__ float swt[K_ * H_];   // per-node head weights
    __shared__ int   sidx[K_];

    const int tid = threadIdx.x;
    const int n  = blockIdx.x;
    const int bb = blockIdx.y;
    const int h = tid >> 6;
    const int f = tid & 63;

    if (tid < K_) {
        sidx[tid] = nidx[n * K_ + tid];
    }
    if (tid >= 32 && tid < 32 + K_ * H_) {
        const int j  = tid - 32;
        const int k  = j >> 3;       // neighbor
        const int hh = j & 7;        // head
        const float d   = dist[n * K_ + k];
        const float lam = (float)(hh + 1) * (1.0f / H_);
        swt[j] = __expf(-d * d * lam * (1.0f / (6.0f * 6.0f)));
    }
    __syncthreads();

    float wk[K_];
    #pragma unroll
    for (int k = 0; k < K_; ++k) wk[k] = swt[k * H_ + h];
    const float bv = bias[f];

    float prev = 0.f;
    #pragma unroll 1
    for (int t = 0; t < T_; ++t) {
        const float* yb = g_y + (long)(bb * T_ + t) * N_ * F_;
        if (tid < K_ * (F_ / 4)) {              // 160 float4 loads
            const int k = tid >> 4;
            const int c = tid & 15;
            ((float4*)sy)[k * 16 + c] =
                ((const float4*)(yb + (long)sidx[k] * F_))[c];
        }
        __syncthreads();

        float acc = 0.f;
        #pragma unroll
        for (int k = 0; k < K_; ++k)
            acc = fmaf(wk[k], sy[k * F_ + f], acc);   // wk in regs, sy conflict-free

        const float blend = (t == 0) ? acc : fmaf(0.8f, acc, 0.2f * prev);
        prev = acc;                               // carry UNBLENDED agg

        out[((long)((bb * T_ + t) * N_) + n) * (H_ * F_) + tid] =
            fmaxf(blend + bv, 0.f);
        __syncthreads();                          // protect sy before next gather
    }
}

// ---------------------------------------------------------------------------
// Inputs (metadata order): x f32[4,12,2000,64], neighbor_dist f32[2000,10],
// W f32[64,64], b f32[64], neighbor_idx i32[2000,10]. Output f32[4,12,2000,8,64].
// ---------------------------------------------------------------------------
extern "C" void kernel_launch(void* const* d_in, const int* in_sizes, int n_in,
                              void* d_out, int out_size) {
    const float* x    = (const float*)d_in[0];
    const float* dist = (const float*)d_in[1];
    const float* W    = (const float*)d_in[2];
    const float* bias = (const float*)d_in[3];
    const int*   nidx = (const int*)d_in[4];
    float*       out  = (float*)d_out;

    k_xw<<<(B_ * T_ * N_) / 64, 256>>>(x, W);

    dim3 g2(N_, B_);
    k_gather<<<g2, 512>>>(dist, bias, nidx, out);
}

// round 3
// speedup vs baseline: 1.2897x; 1.2897x over previous
#include <cuda_runtime.h>
#include <cuda_bf16.h>

#define B_ 4
#define T_ 12
#define N_ 2000
#define K_ 10
#define F_ 64
#define H_ 8
#define NPB 16   // nodes per block in k_gather

// Scratch for y = x @ W^T (24.6 MB). Static __device__ (no cudaMalloc allowed).
__device__ float g_y[B_ * T_ * N_ * F_];

// ---- packed-fp32 helpers (FFMA2 only reachable via PTX) ----------------------
__device__ __forceinline__ unsigned long long pk2(float a, float b) {
    unsigned long long r;
    asm("mov.b64 %0, {%1, %2};" : "=l"(r)
        : "r"(__float_as_uint(a)), "r"(__float_as_uint(b)));
    return r;
}
__device__ __forceinline__ unsigned long long ffma2(unsigned long long a,
                                                    unsigned long long b,
                                                    unsigned long long c) {
    unsigned long long d;
    asm("fma.rn.f32x2 %0, %1, %2, %3;" : "=l"(d) : "l"(a), "l"(b), "l"(c));
    return d;
}
__device__ __forceinline__ float2 upk2(unsigned long long a) {
    unsigned int lo, hi;
    asm("mov.b64 {%0, %1}, %2;" : "=r"(lo), "=r"(hi) : "l"(a));
    return make_float2(__uint_as_float(lo), __uint_as_float(hi));
}

// ---------------------------------------------------------------------------
// Kernel 1: y[row,f] = sum_fp x[row,fp] * W[f,fp].
// 1500 blocks x 256 threads; 64-row tile; thread = 4 rows x 4 f, FFMA2 pairs.
// ---------------------------------------------------------------------------
__global__ __launch_bounds__(256) void k_xw(const float* __restrict__ x,
                                            const float* __restrict__ W) {
    __shared__ float xs[64][68];               // pad 4 floats: 16B-aligned rows, no bank conflict
    __shared__ unsigned long long Wp[64][32];  // Wp[fp][f2] = (W[2f2][fp], W[2f2+1][fp])

    const int tid = threadIdx.x;

    #pragma unroll 2
    for (int j = tid; j < 64 * 32; j += 256) {
        const int fp = j >> 5, f2 = j & 31;
        Wp[fp][f2] = pk2(W[(2 * f2) * 64 + fp], W[(2 * f2 + 1) * 64 + fp]);
    }

    const size_t rbase = (size_t)blockIdx.x * 64;
    const float4* xg = (const float4*)(x + rbase * F_);
    #pragma unroll 2
    for (int j = tid; j < 64 * 16; j += 256) {     // 64 rows x 16 float4, coalesced
        const int r = j >> 4, c = j & 15;
        *(float4*)&xs[r][c * 4] = xg[j];
    }
    __syncthreads();

    const int fx = tid & 15;   // f = fx*4 .. fx*4+3
    const int ry = tid >> 4;   // rows ry*4 .. ry*4+3

    unsigned long long acc[4][2];
    #pragma unroll
    for (int r = 0; r < 4; ++r) { acc[r][0] = 0ull; acc[r][1] = 0ull; }

    #pragma unroll 16
    for (int fp = 0; fp < 64; ++fp) {
        const unsigned long long w01 = Wp[fp][fx * 2];
        const unsigned long long w23 = Wp[fp][fx * 2 + 1];
        #pragma unroll
        for (int r = 0; r < 4; ++r) {
            const float xv = xs[ry * 4 + r][fp];          // 2-addr broadcast
            const unsigned long long xd = pk2(xv, xv);
            acc[r][0] = ffma2(xd, w01, acc[r][0]);
            acc[r][1] = ffma2(xd, w23, acc[r][1]);
        }
    }

    float* yp = g_y + rbase * F_;
    #pragma unroll
    for (int r = 0; r < 4; ++r) {
        const float2 lo = upk2(acc[r][0]);
        const float2 hi = upk2(acc[r][1]);
        *(float4*)&yp[(ry * 4 + r) * F_ + fx * 4] = make_float4(lo.x, lo.y, hi.x, hi.y);
    }
}

// ---------------------------------------------------------------------------
// Kernel 2: register-accumulator gather. Block = 16 nodes x one batch b.
// Thread = (node_local, f4): owns float4 f-chunk for ALL 8 heads.
// No smem staging of y, no barriers in the t-loop. Blend carried in registers
// (prev = UNBLENDED agg[t-1]).
// ---------------------------------------------------------------------------
__global__ __launch_bounds__(256) void k_gather(
    const float* __restrict__ dist,
    const float* __restrict__ bias,
    const int* __restrict__ nidx,          // int32 (JAX x64 disabled)
    float* __restrict__ out) {

    __shared__ unsigned long long swd[NPB][K_][H_];   // dup-packed weights (w,w)
    __shared__ int sidx[NPB][K_];

    const int tid = threadIdx.x;
    const int nl  = tid >> 4;        // node within block
    const int f4  = tid & 15;        // float4 index within F
    const int bb  = blockIdx.y;
    const int n0  = blockIdx.x * NPB;

    if (tid < NPB * K_) {
        sidx[tid / K_][tid % K_] = nidx[n0 * K_ + tid];
    }
    #pragma unroll
    for (int j = tid; j < NPB * K_ * H_; j += 256) {   // 5 per thread
        const int nn = j / (K_ * H_);
        const int rr = j % (K_ * H_);
        const int kk = rr / H_, hh = rr % H_;
        const float d = dist[(n0 + nn) * K_ + kk];
        const float w = __expf(-d * d * (float)(hh + 1) * (1.0f / (H_ * 36.0f)));
        swd[nn][kk][hh] = pk2(w, w);
    }
    __syncthreads();

    const float4 bv = *(const float4*)(bias + f4 * 4);
    const unsigned long long b01 = pk2(bv.x, bv.y);
    const unsigned long long b23 = pk2(bv.z, bv.w);

    unsigned long long prev[H_][2];
    #pragma unroll
    for (int h = 0; h < H_; ++h) { prev[h][0] = 0ull; prev[h][1] = 0ull; }

    const int n = n0 + nl;
    const ulonglong2* wrow[K_];
    #pragma unroll
    for (int k = 0; k < K_; ++k) wrow[k] = (const ulonglong2*)swd[nl][k];

    #pragma unroll 1
    for (int t = 0; t < T_; ++t) {
        const float4* yb = (const float4*)(g_y + (size_t)(bb * T_ + t) * N_ * F_);

        unsigned long long acc[H_][2];
        #pragma unroll
        for (int h = 0; h < H_; ++h) { acc[h][0] = 0ull; acc[h][1] = 0ull; }

        #pragma unroll
        for (int k = 0; k < K_; ++k) {
            const float4 yv = yb[sidx[nl][k] * (F_ / 4) + f4];   // gather, reused 8x
            const unsigned long long y01 = pk2(yv.x, yv.y);
            const unsigned long long y23 = pk2(yv.z, yv.w);
            #pragma unroll
            for (int hp = 0; hp < H_ / 2; ++hp) {
                const ulonglong2 wd = wrow[k][hp];               // LDS.128, 2 heads
                acc[2 * hp + 0][0] = ffma2(y01, wd.x, acc[2 * hp + 0][0]);
                acc[2 * hp + 0][1] = ffma2(y23, wd.x, acc[2 * hp + 0][1]);
                acc[2 * hp + 1][0] = ffma2(y01, wd.y, acc[2 * hp + 1][0]);
                acc[2 * hp + 1][1] = ffma2(y23, wd.y, acc[2 * hp + 1][1]);
            }
        }

        const float c0 = (t == 0) ? 1.0f : 0.8f;
        const float c1 = (t == 0) ? 0.0f : 0.2f;
        const unsigned long long c0d = pk2(c0, c0);
        const unsigned long long c1d = pk2(c1, c1);

        float* ob = out + ((size_t)((bb * T_ + t) * N_) + n) * (H_ * F_) + f4 * 4;
        #pragma unroll
        for (int h = 0; h < H_; ++h) {
            const unsigned long long r01 = ffma2(acc[h][0], c0d, ffma2(prev[h][0], c1d, b01));
            const unsigned long long r23 = ffma2(acc[h][1], c0d, ffma2(prev[h][1], c1d, b23));
            const float2 lo = upk2(r01);
            const float2 hi = upk2(r23);
            *(float4*)(ob + h * F_) =
                make_float4(fmaxf(lo.x, 0.f), fmaxf(lo.y, 0.f),
                            fmaxf(hi.x, 0.f), fmaxf(hi.y, 0.f));
            prev[h][0] = acc[h][0];
            prev[h][1] = acc[h][1];
        }
    }
}

// ---------------------------------------------------------------------------
// Inputs: x f32[4,12,2000,64], neighbor_dist f32[2000,10], W f32[64,64],
// b f32[64], neighbor_idx i32[2000,10]. Output f32[4,12,2000,8,64].
// ---------------------------------------------------------------------------
extern "C" void kernel_launch(void* const* d_in, const int* in_sizes, int n_in,
                              void* d_out, int out_size) {
    const float* x    = (const float*)d_in[0];
    const float* dist = (const float*)d_in[1];
    const float* W    = (const float*)d_in[2];
    const float* bias = (const float*)d_in[3];
    const int*   nidx = (const int*)d_in[4];
    float*       out  = (float*)d_out;

    k_xw<<<(B_ * T_ * N_) / 64, 256>>>(x, W);

    dim3 g2(N_ / NPB, B_);
    k_gather<<<g2, 256>>>(dist, bias, nidx, out);
}

// round 4
// speedup vs baseline: 1.5782x; 1.2237x over previous
#include <cuda_runtime.h>
#include <cuda_bf16.h>

#define B_ 4
#define T_ 12
#define N_ 2000
#define K_ 10
#define F_ 64
#define H_ 8

// Scratch: y = x @ W^T (24.6 MB) + packed-transposed W (16 KB).
__device__ float g_y[B_ * T_ * N_ * F_];
__device__ unsigned long long g_wp[64 * 32];   // g_wp[fp*32+f2] = (W[2f2][fp], W[2f2+1][fp])

// ---- packed-fp32 helpers (FFMA2 only reachable via PTX) ---------------------
__device__ __forceinline__ unsigned long long pk2(float a, float b) {
    unsigned long long r;
    asm("mov.b64 %0, {%1, %2};" : "=l"(r)
        : "r"(__float_as_uint(a)), "r"(__float_as_uint(b)));
    return r;
}
__device__ __forceinline__ unsigned long long ffma2(unsigned long long a,
                                                    unsigned long long b,
                                                    unsigned long long c) {
    unsigned long long d;
    asm("fma.rn.f32x2 %0, %1, %2, %3;" : "=l"(d) : "l"(a), "l"(b), "l"(c));
    return d;
}
__device__ __forceinline__ float2 upk2(unsigned long long a) {
    unsigned int lo, hi;
    asm("mov.b64 {%0, %1}, %2;" : "=r"(lo), "=r"(hi) : "l"(a));
    return make_float2(__uint_as_float(lo), __uint_as_float(hi));
}

// ---------------------------------------------------------------------------
// Prep: build packed W^T once (8 blocks). Pays the strided-read cost here so
// the 750 k_xw blocks read it fully coalesced.
// ---------------------------------------------------------------------------
__global__ void k_prep(const float* __restrict__ W) {
    const int j = blockIdx.x * 256 + threadIdx.x;    // 0..2047
    const int fp = j >> 5, f2 = j & 31;
    g_wp[j] = pk2(W[(2 * f2) * 64 + fp], W[(2 * f2 + 1) * 64 + fp]);
}

// ---------------------------------------------------------------------------
// Kernel 1: y[row,f] = sum_fp x[row,fp] * W[f,fp].
// 750 blocks x 256 threads; 128-row tile; thread = 8 rows x 4 f (FFMA2 pairs).
// Per 4-fp step: 12 LDS.128 feeding 64 FFMA2.
// ---------------------------------------------------------------------------
__global__ __launch_bounds__(256) void k_xw(const float* __restrict__ x) {
    __shared__ float xs[128][64];                  // 32 KB, no pad (reads are broadcasts)
    __shared__ unsigned long long Wp[64 * 32];     // 16 KB

    const int tid = threadIdx.x;
    #pragma unroll
    for (int j = tid; j < 2048; j += 256) Wp[j] = g_wp[j];   // coalesced

    const size_t rbase = (size_t)blockIdx.x * 128;
    const float4* xg = (const float4*)(x + rbase * F_);
    #pragma unroll
    for (int j = tid; j < 128 * 16; j += 256) {              // coalesced
        ((float4*)xs)[j] = xg[j];
    }
    __syncthreads();

    const int fx = tid & 15;       // f chunk: 4 floats = 2 ull
    const int rg = tid >> 4;       // rows rg*8 .. rg*8+7

    unsigned long long acc[8][2];
    #pragma unroll
    for (int r = 0; r < 8; ++r) { acc[r][0] = 0ull; acc[r][1] = 0ull; }

    #pragma unroll 4
    for (int fps = 0; fps < 16; ++fps) {
        const int fp = fps * 4;
        unsigned long long w0[4], w1[4];
        #pragma unroll
        for (int i = 0; i < 4; ++i) {
            const ulonglong2 wv = *(const ulonglong2*)&Wp[(fp + i) * 32 + fx * 2];
            w0[i] = wv.x; w1[i] = wv.y;            // 256B/warp, conflict-free
        }
        #pragma unroll
        for (int r = 0; r < 8; ++r) {
            const float4 xv = *(const float4*)&xs[rg * 8 + r][fp];   // broadcast
            unsigned long long xd;
            xd = pk2(xv.x, xv.x);
            acc[r][0] = ffma2(xd, w0[0], acc[r][0]); acc[r][1] = ffma2(xd, w1[0], acc[r][1]);
            xd = pk2(xv.y, xv.y);
            acc[r][0] = ffma2(xd, w0[1], acc[r][0]); acc[r][1] = ffma2(xd, w1[1], acc[r][1]);
            xd = pk2(xv.z, xv.z);
            acc[r][0] = ffma2(xd, w0[2], acc[r][0]); acc[r][1] = ffma2(xd, w1[2], acc[r][1]);
            xd = pk2(xv.w, xv.w);
            acc[r][0] = ffma2(xd, w0[3], acc[r][0]); acc[r][1] = ffma2(xd, w1[3], acc[r][1]);
        }
    }

    float* yp = g_y + rbase * F_;
    #pragma unroll
    for (int r = 0; r < 8; ++r) {
        const float2 lo = upk2(acc[r][0]);
        const float2 hi = upk2(acc[r][1]);
        *(float4*)&yp[(rg * 8 + r) * F_ + fx * 4] = make_float4(lo.x, lo.y, hi.x, hi.y);
    }
}

// ---------------------------------------------------------------------------
// Kernel 2: gather + heads + blend + relu, fully register-resident.
// Thread = (node nl, head-pair hp, float4 f4). f32x2 packs the HEAD pair, so
// weights pack without duplication and acc+prev are only 16 regs. No smem, no
// barriers; prev carries the UNBLENDED agg[t-1].
// ---------------------------------------------------------------------------
__global__ __launch_bounds__(256, 3) void k_gather(
    const float* __restrict__ dist,
    const float* __restrict__ bias,
    const int* __restrict__ nidx,          // int32 (JAX x64 disabled)
    float* __restrict__ out) {

    const int tid = threadIdx.x;
    const int f4  = tid & 15;
    const int hp  = (tid >> 4) & 3;        // heads 2hp, 2hp+1
    const int nl  = tid >> 6;              // 0..3
    const int bb  = blockIdx.y;
    const int n   = blockIdx.x * 4 + nl;

    int sidx[K_];
    unsigned long long wk[K_];
    const float h0f = (float)(2 * hp + 1);
    const float h1f = (float)(2 * hp + 2);
    #pragma unroll
    for (int k = 0; k < K_; ++k) {
        sidx[k] = __ldg(&nidx[n * K_ + k]) * 16;          // pre-scaled float4 idx
        const float d = __ldg(&dist[n * K_ + k]);
        const float e = -d * d * (1.0f / (H_ * 36.0f));
        wk[k] = pk2(__expf(e * h0f), __expf(e * h1f));    // (w_h0, w_h1)
    }

    const float4 bv = *(const float4*)(bias + f4 * 4);
    const unsigned long long bd[4] = { pk2(bv.x, bv.x), pk2(bv.y, bv.y),
                                       pk2(bv.z, bv.z), pk2(bv.w, bv.w) };

    unsigned long long prev[4] = {0ull, 0ull, 0ull, 0ull};

    #pragma unroll 1
    for (int t = 0; t < T_; ++t) {
        const float4* yb = (const float4*)g_y
                         + (size_t)(bb * T_ + t) * N_ * (F_ / 4) + f4;

        unsigned long long acc[4] = {0ull, 0ull, 0ull, 0ull};
        #pragma unroll
        for (int k = 0; k < K_; ++k) {                    // 10 independent LDG.128
            const float4 yv = __ldg(&yb[sidx[k]]);
            acc[0] = ffma2(pk2(yv.x, yv.x), wk[k], acc[0]);
            acc[1] = ffma2(pk2(yv.y, yv.y), wk[k], acc[1]);
            acc[2] = ffma2(pk2(yv.z, yv.z), wk[k], acc[2]);
            acc[3] = ffma2(pk2(yv.w, yv.w), wk[k], acc[3]);
        }

        const float c0 = (t == 0) ? 1.0f : 0.8f;
        const float c1 = (t == 0) ? 0.0f : 0.2f;
        const unsigned long long c0d = pk2(c0, c0);
        const unsigned long long c1d = pk2(c1, c1);

        float r0[4], r1[4];
        #pragma unroll
        for (int i = 0; i < 4; ++i) {
            const unsigned long long r =
                ffma2(acc[i], c0d, ffma2(prev[i], c1d, bd[i]));
            const float2 v = upk2(r);
            r0[i] = fmaxf(v.x, 0.f);
            r1[i] = fmaxf(v.y, 0.f);
            prev[i] = acc[i];                             // carry UNBLENDED agg
        }

        float* ob = out + ((size_t)((bb * T_ + t) * N_) + n) * (H_ * F_) + f4 * 4;
        *(float4*)(ob + (2 * hp)     * F_) = make_float4(r0[0], r0[1], r0[2], r0[3]);
        *(float4*)(ob + (2 * hp + 1) * F_) = make_float4(r1[0], r1[1], r1[2], r1[3]);
    }
}

// ---------------------------------------------------------------------------
// Inputs: x f32[4,12,2000,64], neighbor_dist f32[2000,10], W f32[64,64],
// b f32[64], neighbor_idx i32[2000,10]. Output f32[4,12,2000,8,64].
// ---------------------------------------------------------------------------
extern "C" void kernel_launch(void* const* d_in, const int* in_sizes, int n_in,
                              void* d_out, int out_size) {
    const float* x    = (const float*)d_in[0];
    const float* dist = (const float*)d_in[1];
    const float* W    = (const float*)d_in[2];
    const float* bias = (const float*)d_in[3];
    const int*   nidx = (const int*)d_in[4];
    float*       out  = (float*)d_out;

    k_prep<<<8, 256>>>(W);
    k_xw<<<(B_ * T_ * N_) / 128, 256>>>(x);

    dim3 g2(N_ / 4, B_);
    k_gather<<<g2, 256>>>(dist, bias, nidx, out);
}

// round 5
// speedup vs baseline: 1.8196x; 1.1529x over previous
#include <cuda_runtime.h>

#define B_ 4
#define T_ 12
#define N_ 2000
#define K_ 10
#define F_ 64
#define H_ 8

// Scratch: y = x @ W^T (24.6 MB). Static __device__ (no cudaMalloc allowed).
__device__ float g_y[B_ * T_ * N_ * F_];

// ---- packed-fp32 helpers (FFMA2 only reachable via PTX) ---------------------
__device__ __forceinline__ unsigned long long pk2(float a, float b) {
    unsigned long long r;
    asm("mov.b64 %0, {%1, %2};" : "=l"(r)
        : "r"(__float_as_uint(a)), "r"(__float_as_uint(b)));
    return r;
}
__device__ __forceinline__ unsigned long long ffma2(unsigned long long a,
                                                    unsigned long long b,
                                                    unsigned long long c) {
    unsigned long long d;
    asm("fma.rn.f32x2 %0, %1, %2, %3;" : "=l"(d) : "l"(a), "l"(b), "l"(c));
    return d;
}
__device__ __forceinline__ float2 upk2(unsigned long long a) {
    unsigned int lo, hi;
    asm("mov.b64 {%0, %1}, %2;" : "=r"(lo), "=r"(hi) : "l"(a));
    return make_float2(__uint_as_float(lo), __uint_as_float(hi));
}

// ---------------------------------------------------------------------------
// Kernel 1: y[row,f] = sum_fp x[row,fp] * W[f,fp].
// 750 blocks x 256 threads; 128-row tile; thread = 8 rows x 4 f (FFMA2 pairs).
// W pack is done in-kernel (W is 16 KB, L2-resident) — no prep kernel.
// ---------------------------------------------------------------------------
__global__ __launch_bounds__(256) void k_xw(const float* __restrict__ x,
                                            const float* __restrict__ W) {
    __shared__ float xs[128][64];                  // 32 KB
    __shared__ unsigned long long Wp[64][32];      // 16 KB: Wp[fp][f2]=(W[2f2][fp],W[2f2+1][fp])

    const int tid = threadIdx.x;

    // Build Wp: thread = (f2 = tid>>3, col-group cg = tid&7 covering fp cg*8..+7).
    {
        const int f2 = tid >> 3, cg = tid & 7;
        const float* ra = W + (2 * f2) * 64 + cg * 8;
        const float* rb = W + (2 * f2 + 1) * 64 + cg * 8;
        const float4 a0 = *(const float4*)ra;
        const float4 a1 = *(const float4*)(ra + 4);
        const float4 b0 = *(const float4*)rb;
        const float4 b1 = *(const float4*)(rb + 4);
        Wp[cg * 8 + 0][f2] = pk2(a0.x, b0.x);
        Wp[cg * 8 + 1][f2] = pk2(a0.y, b0.y);
        Wp[cg * 8 + 2][f2] = pk2(a0.z, b0.z);
        Wp[cg * 8 + 3][f2] = pk2(a0.w, b0.w);
        Wp[cg * 8 + 4][f2] = pk2(a1.x, b1.x);
        Wp[cg * 8 + 5][f2] = pk2(a1.y, b1.y);
        Wp[cg * 8 + 6][f2] = pk2(a1.z, b1.z);
        Wp[cg * 8 + 7][f2] = pk2(a1.w, b1.w);
    }

    const size_t rbase = (size_t)blockIdx.x * 128;
    const float4* xg = (const float4*)(x + rbase * F_);
    #pragma unroll
    for (int j = tid; j < 128 * 16; j += 256) {              // coalesced
        ((float4*)xs)[j] = xg[j];
    }
    __syncthreads();

    const int fx = tid & 15;       // f chunk: 4 floats = 2 ull
    const int rg = tid >> 4;       // rows rg*8 .. rg*8+7

    unsigned long long acc[8][2];
    #pragma unroll
    for (int r = 0; r < 8; ++r) { acc[r][0] = 0ull; acc[r][1] = 0ull; }

    #pragma unroll 4
    for (int fps = 0; fps < 16; ++fps) {
        const int fp = fps * 4;
        unsigned long long w0[4], w1[4];
        #pragma unroll
        for (int i = 0; i < 4; ++i) {
            const ulonglong2 wv = *(const ulonglong2*)&Wp[fp + i][fx * 2];
            w0[i] = wv.x; w1[i] = wv.y;            // conflict-free
        }
        #pragma unroll
        for (int r = 0; r < 8; ++r) {
            const float4 xv = *(const float4*)&xs[rg * 8 + r][fp];   // broadcast
            unsigned long long xd;
            xd = pk2(xv.x, xv.x);
            acc[r][0] = ffma2(xd, w0[0], acc[r][0]); acc[r][1] = ffma2(xd, w1[0], acc[r][1]);
            xd = pk2(xv.y, xv.y);
            acc[r][0] = ffma2(xd, w0[1], acc[r][0]); acc[r][1] = ffma2(xd, w1[1], acc[r][1]);
            xd = pk2(xv.z, xv.z);
            acc[r][0] = ffma2(xd, w0[2], acc[r][0]); acc[r][1] = ffma2(xd, w1[2], acc[r][1]);
            xd = pk2(xv.w, xv.w);
            acc[r][0] = ffma2(xd, w0[3], acc[r][0]); acc[r][1] = ffma2(xd, w1[3], acc[r][1]);
        }
    }

    float* yp = g_y + rbase * F_;
    #pragma unroll
    for (int r = 0; r < 8; ++r) {
        const float2 lo = upk2(acc[r][0]);
        const float2 hi = upk2(acc[r][1]);
        *(float4*)&yp[(rg * 8 + r) * F_ + fx * 4] = make_float4(lo.x, lo.y, hi.x, hi.y);
    }
}

// ---------------------------------------------------------------------------
// Kernel 2: gather + heads + blend + relu. Thread = (node nl, head-pair hp,
// float4 f4). f32x2 packs ADJACENT f's, so LDG.128 register pairs feed FFMA2
// with ZERO mov overhead; weight duplication is hoisted to the prologue.
// Inner loop per k: 1 LDG.128 + 4 FFMA2. No barriers in the t-loop.
// prev carries the UNBLENDED agg[t-1]; t=0 peeled so blend consts hoist.
// ---------------------------------------------------------------------------
__device__ __forceinline__ void gather10(const float4* __restrict__ yb,
                                         const int* __restrict__ sx,
                                         const unsigned long long* wd0,
                                         const unsigned long long* wd1,
                                         unsigned long long acc[2][2]) {
    acc[0][0] = 0ull; acc[0][1] = 0ull; acc[1][0] = 0ull; acc[1][1] = 0ull;
    #pragma unroll
    for (int k = 0; k < K_; ++k) {                 // 10 independent LDG.128
        const float4 yv = __ldg(&yb[sx[k]]);
        const unsigned long long y01 = pk2(yv.x, yv.y);   // register-pair, no MOV
        const unsigned long long y23 = pk2(yv.z, yv.w);
        acc[0][0] = ffma2(y01, wd0[k], acc[0][0]);
        acc[0][1] = ffma2(y23, wd0[k], acc[0][1]);
        acc[1][0] = ffma2(y01, wd1[k], acc[1][0]);
        acc[1][1] = ffma2(y23, wd1[k], acc[1][1]);
    }
}

__global__ __launch_bounds__(256, 3) void k_gather(
    const float* __restrict__ dist,
    const float* __restrict__ bias,
    const int* __restrict__ nidx,          // int32 (JAX x64 disabled)
    float* __restrict__ out) {

    __shared__ int sidx[4][K_];            // pre-scaled float4 indices, per node

    const int tid = threadIdx.x;
    const int f4  = tid & 15;
    const int hp  = (tid >> 4) & 3;        // heads 2hp, 2hp+1
    const int nl  = tid >> 6;              // 0..3
    const int bb  = blockIdx.y;
    const int n   = blockIdx.x * 4 + nl;

    if (tid < 4 * K_) {
        sidx[tid / K_][tid % K_] = __ldg(&nidx[(blockIdx.x * 4 + tid / K_) * K_ + tid % K_]) * 16;
    }

    // Duplicated weight pairs for this thread's two heads (hoisted, 20 ull).
    unsigned long long wd0[K_], wd1[K_];
    const float h0f = (float)(2 * hp + 1);
    const float h1f = (float)(2 * hp + 2);
    #pragma unroll
    for (int k = 0; k < K_; ++k) {
        const float d = __ldg(&dist[n * K_ + k]);
        const float e = -d * d * (1.0f / (H_ * 36.0f));
        const float w0 = __expf(e * h0f);
        const float w1 = __expf(e * h1f);
        wd0[k] = pk2(w0, w0);
        wd1[k] = pk2(w1, w1);
    }
    __syncthreads();

    const float4 bv = *(const float4*)(bias + f4 * 4);
    const unsigned long long b01 = pk2(bv.x, bv.y);       // natural pairs
    const unsigned long long b23 = pk2(bv.z, bv.w);

    const int* sx = sidx[nl];
    const size_t obase = ((size_t)(bb * T_ * N_) + n) * (H_ * F_) + (2 * hp) * F_ + f4 * 4;
    const float4* ybase = (const float4*)g_y + (size_t)(bb * T_) * N_ * (F_ / 4) + f4;

    unsigned long long prev[2][2];
    unsigned long long acc[2][2];

    // ---- t = 0: out = relu(acc + b) ----
    gather10(ybase, sx, wd0, wd1, acc);
    {
        float* ob = out + obase;
        #pragma unroll
        for (int h = 0; h < 2; ++h) {
            const float2 lo = upk2(ffma2(acc[h][0], pk2(1.f, 1.f), b01));
            const float2 hi = upk2(ffma2(acc[h][1], pk2(1.f, 1.f), b23));
            *(float4*)(ob + h * F_) =
                make_float4(fmaxf(lo.x, 0.f), fmaxf(lo.y, 0.f),
                            fmaxf(hi.x, 0.f), fmaxf(hi.y, 0.f));
            prev[h][0] = acc[h][0]; prev[h][1] = acc[h][1];
        }
    }

    const unsigned long long c0d = pk2(0.8f, 0.8f);
    const unsigned long long c1d = pk2(0.2f, 0.2f);

    #pragma unroll 1
    for (int t = 1; t < T_; ++t) {
        gather10(ybase + (size_t)t * N_ * (F_ / 4), sx, wd0, wd1, acc);

        float* ob = out + obase + (size_t)t * N_ * (H_ * F_);
        #pragma unroll
        for (int h = 0; h < 2; ++h) {
            const float2 lo = upk2(ffma2(acc[h][0], c0d, ffma2(prev[h][0], c1d, b01)));
            const float2 hi = upk2(ffma2(acc[h][1], c0d, ffma2(prev[h][1], c1d, b23)));
            *(float4*)(ob + h * F_) =
                make_float4(fmaxf(lo.x, 0.f), fmaxf(lo.y, 0.f),
                            fmaxf(hi.x, 0.f), fmaxf(hi.y, 0.f));
            prev[h][0] = acc[h][0]; prev[h][1] = acc[h][1];   // UNBLENDED carry
        }
    }
}

// ---------------------------------------------------------------------------
// Inputs: x f32[4,12,2000,64], neighbor_dist f32[2000,10], W f32[64,64],
// b f32[64], neighbor_idx i32[2000,10]. Output f32[4,12,2000,8,64].
// ---------------------------------------------------------------------------
extern "C" void kernel_launch(void* const* d_in, const int* in_sizes, int n_in,
                              void* d_out, int out_size) {
    const float* x    = (const float*)d_in[0];
    const float* dist = (const float*)d_in[1];
    const float* W    = (const float*)d_in[2];
    const float* bias = (const float*)d_in[3];
    const int*   nidx = (const int*)d_in[4];
    float*       out  = (float*)d_out;

    k_xw<<<(B_ * T_ * N_) / 128, 256>>>(x, W);

    dim3 g2(N_ / 4, B_);
    k_gather<<<g2, 256>>>(dist, bias, nidx, out);
}